// round 4
// baseline (speedup 1.0000x reference)
#include <cuda_runtime.h>

namespace {

constexpr int Bn = 16;
constexpr int Ln = 2048;
constexpr int Gn = 8;
constexpr int Pn = 8;
constexpr int Kn = 64;
constexpr float kClamp = 15.0f;

constexpr int LT = 64;            // l-tile size
constexpr int NT = Ln / LT;       // 32 tiles
constexpr int THREADS = 256;

// Deterministic partial-score buffer: [tile][b][j]
__device__ float g_partial[NT * Bn * Pn];
// Input-mask dtype: 0 = bytes, 1 = int32, 2 = float32
__device__ int g_mask_mode;

__global__ void detect_kernel(const unsigned int* __restrict__ mask_raw) {
    // single thread; scans 1024 words = 4096 bytes
    bool all01 = true;       // every word 0 or 1        -> int32
    bool allf = true;        // every word 0 or 0x3F800000 -> float32
    for (int i = 0; i < 1024; ++i) {
        unsigned int w = mask_raw[i];
        if (w > 1u) all01 = false;
        if (w != 0u && w != 0x3F800000u) allf = false;
    }
    g_mask_mode = all01 ? 1 : (allf ? 2 : 0);
}

__global__ void init_kernel(const float* __restrict__ xn_in,
                            const void* __restrict__ mask_raw,
                            float* __restrict__ out,
                            int out_float_mask) {
    int i = blockIdx.x * blockDim.x + threadIdx.x;
    if (i < Bn * Ln * 3) out[i] = xn_in[i];
    if (i < Bn * Ln) {
        int mode = g_mask_mode;
        int v;
        if (mode == 1)      v = ((const int*)mask_raw)[i] != 0;
        else if (mode == 2) v = ((const float*)mask_raw)[i] != 0.0f;
        else                v = ((const unsigned char*)mask_raw)[i] != 0;
        if (out_float_mask) out[Bn * Ln * 3 + i] = v ? 1.0f : 0.0f;
        else ((unsigned char*)(out + Bn * Ln * 3))[i] = (unsigned char)v;
    }
}

__global__ __launch_bounds__(THREADS) void score_kernel(
        const float* __restrict__ xp,
        const float* __restrict__ out,      // x_nat working copy at offset 0
        const int* __restrict__ am,
        int g) {
    __shared__ float dp_s[Kn][LT];          // pred distances: base-k x l
    __shared__ float dn_s[Kn][LT];          // native distances: base-k x l
    __shared__ float cmask_s[LT];
    __shared__ short pos_s[Ln];             // position -> index within a0, else -1
    __shared__ unsigned char sig_s[Pn * Kn];// sigma_j(k)
    __shared__ float bp_s[Kn][3];           // base pred coords
    __shared__ float bn_s[Kn][3];           // base native coords
    __shared__ float red_s[Pn * LT];

    const float* xn = out;
    const int b = blockIdx.x / NT;
    const int t = blockIdx.x % NT;
    const int tid = threadIdx.x;

    for (int i = tid; i < Ln; i += THREADS) pos_s[i] = -1;
    __syncthreads();

    const int* arow = am + g * Pn * Kn;
    if (tid < Kn) {
        int p0 = arow[tid];                 // a0[k]
        pos_s[p0] = (short)tid;
        const float* q = xp + ((long long)b * Ln + p0) * 3;
        bp_s[tid][0] = q[0]; bp_s[tid][1] = q[1]; bp_s[tid][2] = q[2];
        const float* r = xn + ((long long)b * Ln + p0) * 3;
        bn_s[tid][0] = r[0]; bn_s[tid][1] = r[1]; bn_s[tid][2] = r[2];
    }
    __syncthreads();

    // sigma_j(k) = index of a[j,k] within a0 (a[j] is a permutation of a0)
    for (int i = tid; i < Pn * Kn; i += THREADS) {
        int idx = arow[i];
        short m = pos_s[idx];
        sig_s[i] = (unsigned char)(m < 0 ? 0 : m);
    }

    // Phase 1: distance tiles. Each thread owns one l (tid % LT), 4 threads per l cover k.
    const int l = tid % LT;
    const int lg = t * LT + l;
    {
        const float* q = xp + ((long long)b * Ln + lg) * 3;
        float qx = q[0], qy = q[1], qz = q[2];
        const float* r = xn + ((long long)b * Ln + lg) * 3;
        float nx = r[0], ny = r[1], nz = r[2];
        if (tid < LT) cmask_s[l] = (pos_s[lg] >= 0) ? 0.0f : 1.0f;
        for (int k = tid / LT; k < Kn; k += THREADS / LT) {
            float dx = bp_s[k][0] - qx, dy = bp_s[k][1] - qy, dz = bp_s[k][2] - qz;
            dp_s[k][l] = sqrtf(dx * dx + dy * dy + dz * dz);
            float ex = bn_s[k][0] - nx, ey = bn_s[k][1] - ny, ez = bn_s[k][2] - nz;
            dn_s[k][l] = sqrtf(ex * ex + ey * ey + ez * ez);
        }
    }
    __syncthreads();

    // Phase 2: per (j, l) accumulate sum_k min((dp[k,l] - dn[sigma_j(k),l])^2, CLAMP)
    for (int item = tid; item < Pn * LT; item += THREADS) {
        int j = item / LT;
        int li = item % LT;
        const unsigned char* sj = sig_s + j * Kn;
        float s = 0.0f;
        #pragma unroll 8
        for (int k = 0; k < Kn; ++k) {
            float d = dp_s[k][li] - dn_s[sj[k]][li];
            float d2 = d * d;
            s += fminf(d2, kClamp);
        }
        red_s[item] = s * cmask_s[li];
    }
    __syncthreads();

    // Reduce over l within tile; write deterministic partials.
    if (tid < Pn) {
        float v = 0.0f;
        for (int li = 0; li < LT; ++li) v += red_s[tid * LT + li];
        g_partial[(t * Bn + b) * Pn + tid] = v;
    }
}

__global__ void update_kernel(float* __restrict__ out,
                              const int* __restrict__ am,
                              int g, int out_float_mask) {
    const int b = blockIdx.x;
    const int tid = threadIdx.x;   // 64 threads
    __shared__ float s_s[Pn];
    __shared__ int bj_s;

    if (tid < Pn) {
        float v = 0.0f;
        for (int t = 0; t < NT; ++t) v += g_partial[(t * Bn + b) * Pn + tid];
        s_s[tid] = v;
    }
    __syncthreads();
    if (tid == 0) {
        float best = s_s[0];
        int bi = 0;
        for (int j = 1; j < Pn; ++j) {
            if (s_s[j] < best) { best = s_s[j]; bi = j; }  // first-min tie-break
        }
        bj_s = bi;
    }
    __syncthreads();

    const int* arow = am + g * Pn * Kn;
    int a0 = arow[tid];
    int aj = arow[bj_s * Kn + tid];

    float* xn = out;
    // gather (pre-update values), then scatter; the two index sets are equal as sets,
    // so a block-wide barrier between read and write is required and sufficient.
    float cx = xn[((long long)b * Ln + aj) * 3 + 0];
    float cy = xn[((long long)b * Ln + aj) * 3 + 1];
    float cz = xn[((long long)b * Ln + aj) * 3 + 2];
    float mf = 0.0f; unsigned char mb = 0;
    if (out_float_mask) mf = out[Bn * Ln * 3 + b * Ln + aj];
    else mb = ((unsigned char*)(out + Bn * Ln * 3))[b * Ln + aj];
    __syncthreads();
    xn[((long long)b * Ln + a0) * 3 + 0] = cx;
    xn[((long long)b * Ln + a0) * 3 + 1] = cy;
    xn[((long long)b * Ln + a0) * 3 + 2] = cz;
    if (out_float_mask) out[Bn * Ln * 3 + b * Ln + a0] = mf;
    else ((unsigned char*)(out + Bn * Ln * 3))[b * Ln + a0] = mb;
}

} // namespace

extern "C" void kernel_launch(void* const* d_in, const int* in_sizes, int n_in,
                              void* d_out, int out_size) {
    const float* xp = (const float*)d_in[0];
    const float* xn = (const float*)d_in[1];
    const void* mask = d_in[2];
    const int* am = (const int*)d_in[3];
    float* out = (float*)d_out;

    (void)in_sizes; (void)n_in;

    // Output-1 encoding: unified float32 buffer (mask as 0.0/1.0 floats) iff
    // out_size counts 32768 4-byte mask slots; otherwise packed bool bytes at
    // byte offset B*L*3*4.
    const int out_float_mask = (out_size == Bn * Ln * 3 + Bn * Ln) ? 1 : 0;

    detect_kernel<<<1, 1>>>((const unsigned int*)mask);
    init_kernel<<<(Bn * Ln * 3 + 255) / 256, 256>>>(xn, mask, out, out_float_mask);
    for (int g = 0; g < Gn; ++g) {
        score_kernel<<<Bn * NT, THREADS>>>(xp, out, am, g);
        update_kernel<<<Bn, Kn>>>(out, am, g, out_float_mask);
    }
}

// round 5
// speedup vs baseline: 1.0017x; 1.0017x over previous
#include <cuda_runtime.h>

namespace {

constexpr int Bn = 16;
constexpr int Ln = 2048;
constexpr int Gn = 8;
constexpr int Pn = 8;
constexpr int Kn = 64;
constexpr float kClamp = 15.0f;

constexpr int LT = 128;             // l-tile size
constexpr int NTb = Ln / LT;        // 16 tiles
constexpr int GRID = Bn * NTb;      // 256 blocks
constexpr int THREADS = 128;        // one thread per li
constexpr int DPs = 68;             // dp row stride (floats), 16B-aligned, conflict-free
constexpr int DNs = 65;             // dn row stride (floats), conflict-free

__device__ float g_partial[2][Bn][NTb][Pn];
__device__ unsigned g_count;
__device__ unsigned g_gen;

struct __align__(16) Smem {
    float dp[LT][DPs];              // [li][k] pred distances
    float dn[LT][DNs];              // [li][k] native distances
    float tx[LT][6];                // tile coords: pred xyz, native xyz
    float bp[Kn][3];                // base pred coords
    float bnv[Kn][3];               // base native coords
    float red[Pn][LT + 1];          // per-li partial sums (padded)
    float cmask[LT];
    float ssum[Pn];
    short pos[Ln];                  // position -> index in a0, else -1
    unsigned char sig[Pn * Kn];     // sigma_j(k)
    unsigned char mb[Kn];           // base mask values
    int bj;
};

__device__ __forceinline__ float vldf(const float* p) {
    return *(volatile const float*)p;
}
__device__ __forceinline__ unsigned char vldb(const unsigned char* p) {
    return *(volatile const unsigned char*)p;
}

__device__ __forceinline__ void grid_sync() {
    __syncthreads();
    if (threadIdx.x == 0) {
        __threadfence();
        unsigned gen = atomicAdd(&g_gen, 0u);        // snapshot BEFORE arrive
        unsigned arrived = atomicAdd(&g_count, 1u);
        if (arrived == GRID - 1) {
            atomicExch(&g_count, 0u);
            __threadfence();
            atomicAdd(&g_gen, 1u);
        } else {
            volatile unsigned* vg = &g_gen;
            while (*vg == gen) { __nanosleep(100); }
            __threadfence();
        }
    }
    __syncthreads();
}

__global__ __launch_bounds__(THREADS) void fused_kernel(
        const float* __restrict__ xp,
        const float* __restrict__ xn_in,
        const void*  __restrict__ mask_raw,
        const int*   __restrict__ am,
        float* out, int ofm) {
    extern __shared__ char smem_raw[];
    Smem& S = *reinterpret_cast<Smem*>(smem_raw);

    const int tid = threadIdx.x;
    const int blk = blockIdx.x;
    const int b = blk / NTb;
    const int t = blk % NTb;
    float* xnat = out;
    float* mkf = out + Bn * Ln * 3;
    unsigned char* mkb = (unsigned char*)(out + Bn * Ln * 3);

    // ---- detect input-mask dtype (each block independently; deterministic) ----
    int all01 = 1, allf = 1;
    {
        const unsigned* mw = (const unsigned*)mask_raw;
        for (int i = tid; i < 1024; i += THREADS) {
            unsigned w = __ldg(mw + i);
            if (w > 1u) all01 = 0;
            if (w != 0u && w != 0x3F800000u) allf = 0;
        }
    }
    all01 = __syncthreads_and(all01);
    allf = __syncthreads_and(allf);
    const int mode = all01 ? 1 : (allf ? 2 : 0);

    // ---- init: copy coords + convert mask into out ----
    for (int i = blk * THREADS + tid; i < Bn * Ln * 3; i += GRID * THREADS)
        out[i] = xn_in[i];
    for (int i = blk * THREADS + tid; i < Bn * Ln; i += GRID * THREADS) {
        int v;
        if (mode == 1)      v = ((const int*)mask_raw)[i] != 0;
        else if (mode == 2) v = ((const float*)mask_raw)[i] != 0.0f;
        else                v = ((const unsigned char*)mask_raw)[i] != 0;
        if (ofm) mkf[i] = v ? 1.0f : 0.0f;
        else     mkb[i] = (unsigned char)v;
    }
    grid_sync();

    for (int g = 0; g < Gn; ++g) {
        const int* arow = am + g * Pn * Kn;

        for (int i = tid; i < Ln; i += THREADS) S.pos[i] = -1;
        __syncthreads();

        if (tid < Kn) {
            int p0 = arow[tid];
            S.pos[p0] = (short)tid;
            const float* q = xp + (b * Ln + p0) * 3;
            S.bp[tid][0] = q[0]; S.bp[tid][1] = q[1]; S.bp[tid][2] = q[2];
            const float* r = xnat + (b * Ln + p0) * 3;
            S.bnv[tid][0] = vldf(r + 0); S.bnv[tid][1] = vldf(r + 1); S.bnv[tid][2] = vldf(r + 2);
            S.mb[tid] = ofm ? (unsigned char)(vldf(mkf + b * Ln + p0) != 0.0f)
                            : vldb(mkb + b * Ln + p0);
        }
        __syncthreads();

        for (int i = tid; i < Pn * Kn; i += THREADS) {
            short m = S.pos[arow[i]];
            S.sig[i] = (unsigned char)(m < 0 ? 0 : m);
        }
        // tile coords + column mask (thread = li)
        {
            const int lg = t * LT + tid;
            const float* q = xp + (b * Ln + lg) * 3;
            S.tx[tid][0] = q[0]; S.tx[tid][1] = q[1]; S.tx[tid][2] = q[2];
            const float* r = xnat + (b * Ln + lg) * 3;
            S.tx[tid][3] = vldf(r + 0); S.tx[tid][4] = vldf(r + 1); S.tx[tid][5] = vldf(r + 2);
            S.cmask[tid] = (S.pos[lg] >= 0) ? 0.0f : 1.0f;
        }
        __syncthreads();

        // ---- phase 1: distance tiles (threads 0-63: dp, 64-127: dn) ----
        if (tid < Kn) {
            const int k = tid;
            const float bx = S.bp[k][0], by = S.bp[k][1], bz = S.bp[k][2];
            #pragma unroll 8
            for (int li = 0; li < LT; ++li) {
                float dx = bx - S.tx[li][0], dy = by - S.tx[li][1], dz = bz - S.tx[li][2];
                S.dp[li][k] = sqrtf(dx * dx + dy * dy + dz * dz);
            }
        } else {
            const int k = tid - Kn;
            const float bx = S.bnv[k][0], by = S.bnv[k][1], bz = S.bnv[k][2];
            #pragma unroll 8
            for (int li = 0; li < LT; ++li) {
                float dx = bx - S.tx[li][3], dy = by - S.tx[li][4], dz = bz - S.tx[li][5];
                S.dn[li][k] = sqrtf(dx * dx + dy * dy + dz * dz);
            }
        }
        __syncthreads();

        // ---- phase 2: scores. thread = li; dp row cached in regs ----
        {
            float dpr[Kn];
            const float4* dpv = (const float4*)(&S.dp[tid][0]);
            #pragma unroll
            for (int c = 0; c < Kn / 4; ++c) {
                float4 v = dpv[c];
                dpr[4 * c + 0] = v.x; dpr[4 * c + 1] = v.y;
                dpr[4 * c + 2] = v.z; dpr[4 * c + 3] = v.w;
            }
            const float* dnrow = &S.dn[tid][0];
            const unsigned* sigw = (const unsigned*)S.sig;
            const float cm = S.cmask[tid];
            #pragma unroll 1
            for (int j = 0; j < Pn; ++j) {
                float acc = 0.0f;
                #pragma unroll
                for (int c = 0; c < Kn / 4; ++c) {
                    unsigned w = sigw[j * (Kn / 4) + c];
                    float d0 = dpr[4 * c + 0] - dnrow[w & 255u];
                    acc += fminf(d0 * d0, kClamp);
                    float d1 = dpr[4 * c + 1] - dnrow[(w >> 8) & 255u];
                    acc += fminf(d1 * d1, kClamp);
                    float d2 = dpr[4 * c + 2] - dnrow[(w >> 16) & 255u];
                    acc += fminf(d2 * d2, kClamp);
                    float d3 = dpr[4 * c + 3] - dnrow[(w >> 24) & 255u];
                    acc += fminf(d3 * d3, kClamp);
                }
                S.red[j][tid] = acc * cm;
            }
        }
        __syncthreads();

        if (tid < Pn) {
            float v = 0.0f;
            for (int li = 0; li < LT; ++li) v += S.red[tid][li];
            g_partial[g & 1][b][t][tid] = v;
        }
        grid_sync();

        // ---- selection (redundant, identical in every block of b) ----
        if (tid < Pn) {
            float v = 0.0f;
            for (int tt = 0; tt < NTb; ++tt)
                v += vldf(&g_partial[g & 1][b][tt][tid]);
            S.ssum[tid] = v;
        }
        __syncthreads();
        if (tid == 0) {
            float best = S.ssum[0];
            int bi = 0;
            for (int j = 1; j < Pn; ++j)
                if (S.ssum[j] < best) { best = S.ssum[j]; bi = j; }
            S.bj = bi;
        }
        __syncthreads();

        // ---- update (redundant identical writes from every block of b) ----
        if (tid < Kn) {
            int a0 = arow[tid];
            int sk = S.sig[S.bj * Kn + tid];
            float* w = xnat + (b * Ln + a0) * 3;
            w[0] = S.bnv[sk][0]; w[1] = S.bnv[sk][1]; w[2] = S.bnv[sk][2];
            if (ofm) mkf[b * Ln + a0] = S.mb[sk] ? 1.0f : 0.0f;
            else     mkb[b * Ln + a0] = S.mb[sk];
        }
        __syncthreads();   // own writes visible block-wide before next group's reads
    }
}

} // namespace

extern "C" void kernel_launch(void* const* d_in, const int* in_sizes, int n_in,
                              void* d_out, int out_size) {
    const float* xp = (const float*)d_in[0];
    const float* xn = (const float*)d_in[1];
    const void* mask = d_in[2];
    const int* am = (const int*)d_in[3];
    float* out = (float*)d_out;

    (void)in_sizes; (void)n_in;

    const int ofm = (out_size == Bn * Ln * 3 + Bn * Ln) ? 1 : 0;

    static int configured = 0;
    if (!configured) {
        cudaFuncSetAttribute(fused_kernel,
                             cudaFuncAttributeMaxDynamicSharedMemorySize,
                             (int)sizeof(Smem));
        configured = 1;
    }
    fused_kernel<<<GRID, THREADS, sizeof(Smem)>>>(xp, xn, mask, am, out, ofm);
}